// round 7
// baseline (speedup 1.0000x reference)
#include <cuda_runtime.h>

// Gegenbauer (alpha=0.5 -> Legendre) embedding: out[row, i-1] = C_i(x[row]), i=1..64.
// Round 7: n = 2,000,000 = 128*15625 exactly -> unguarded full-tile kernel
// (no bounds predicates in the hot path). Two 32-column passes through padded
// smem (PAD=9 f4, conflict-free STS/LDS), fully coalesced 128B-line stores.

#define DIM_OUT 64
#define RPB 128          // rows per block == threads
#define HF4 8            // float4 per half-row (32 floats = 128B)
#define PAD 9            // smem row stride in float4

template <bool FULL>
__global__ void __launch_bounds__(RPB) geg_kernel(const float* __restrict__ x,
                                                  float* __restrict__ out,
                                                  int n) {
    __shared__ float4 s[RPB * PAD];   // 18,432 B

    const int tid = threadIdx.x;
    const size_t row = (size_t)blockIdx.x * RPB + tid;
    const float xv = FULL ? x[row] : ((row < (size_t)n) ? x[row] : 0.0f);

    float4* __restrict__ o4 = reinterpret_cast<float4*>(out);
    const size_t base_f4 = (size_t)blockIdx.x * RPB * (DIM_OUT / 4);
    const size_t total_f4 = ((size_t)n * DIM_OUT) / 4;

    float prev2 = 1.0f;   // C_0
    float prev  = xv;     // C_1 (alpha = 0.5)

    #pragma unroll
    for (int pass = 0; pass < 2; ++pass) {
        // ---- compute 32 coefficients, streaming to smem 4 at a time ----
        #pragma unroll
        for (int g = 0; g < HF4; ++g) {
            float4 v;
            float* vp = reinterpret_cast<float*>(&v);
            #pragma unroll
            for (int e = 0; e < 4; ++e) {
                const int k = pass * 32 + g * 4 + e;   // slot holds C_{k+1}
                float ci;
                if (k == 0) {
                    ci = xv;                            // C_1
                } else {
                    const int i = k + 1;
                    const float A = (float)(2 * i - 1);
                    const float B = (float)(1 - i);
                    const float r = 1.0f / (float)i;
                    ci = (A * xv * prev + B * prev2) * r;
                    prev2 = prev;
                    prev  = ci;
                }
                vp[e] = ci;
            }
            s[tid * PAD + g] = v;   // conflict-free: (9*tid+g)%8 distinct per phase
        }
        __syncthreads();

        // ---- coalesced copy-out of this 32-column block ----
        #pragma unroll
        for (int j = 0; j < HF4; ++j) {
            const int f = j * RPB + tid;   // index within 128x8 f4 tile
            const int r = f >> 3;          // row within block
            const int cq = f & 7;          // f4 column within half-row
            const size_t g = base_f4 + (size_t)r * (DIM_OUT / 4) + pass * HF4 + cq;
            if (FULL) {
                o4[g] = s[r * PAD + cq];
            } else if (g < total_f4) {
                o4[g] = s[r * PAD + cq];
            }
        }
        if (pass == 0) __syncthreads();    // guard smem reuse; none after last pass
    }
}

extern "C" void kernel_launch(void* const* d_in, const int* in_sizes, int n_in,
                              void* d_out, int out_size) {
    const float* x = (const float*)d_in[0];
    float* out = (float*)d_out;
    int n = in_sizes[0];   // 2,000,000 rows = 15625 full tiles of 128
    int blocks = (n + RPB - 1) / RPB;
    if (n % RPB == 0) {
        geg_kernel<true><<<blocks, RPB>>>(x, out, n);
    } else {
        geg_kernel<false><<<blocks, RPB>>>(x, out, n);
    }
}